// round 15
// baseline (speedup 1.0000x reference)
#include <cuda_runtime.h>
#include <cuda_bf16.h>
#include <cstdint>

#define NNODES 50000
#define DIN    256
#define DH     256
#define DOUT   128
#define MAX_E  1600000
#define NB     ((NNODES + 1023) / 1024)
#define MTILES ((NNODES + 127) / 128)

// ---------------- static device scratch ----------------
__device__ float g_h1[(size_t)NNODES * DH];
__device__ float g_o1[(size_t)NNODES * DH];
__device__ float g_h2[(size_t)NNODES * DOUT];
__device__ float g_dinv[NNODES];
__device__ int   g_cnt[NNODES];
__device__ int   g_rowptr[NNODES + 1];
__device__ int   g_cursor[NNODES];
__device__ int   g_csrc[MAX_E];
__device__ int   g_bsum[NB];
__device__ int   g_is64;
__device__ __nv_bfloat16 g_w1hi[DH * DIN];
__device__ __nv_bfloat16 g_w1lo[DH * DIN];
__device__ __nv_bfloat16 g_w2hi[DOUT * DH];
__device__ __nv_bfloat16 g_w2lo[DOUT * DH];

// ---------------- small helpers ----------------
__device__ __forceinline__ uint32_t smem_u32(const void* p) {
    uint32_t a;
    asm("{ .reg .u64 t; cvta.to.shared.u64 t, %1; cvt.u32.u64 %0, t; }" : "=r"(a) : "l"(p));
    return a;
}
__device__ __forceinline__ uint32_t pack_bf16x2(float a, float b) {
    __nv_bfloat162 t;
    t.x = __float2bfloat16(a);
    t.y = __float2bfloat16(b);
    return *(uint32_t*)&t;
}
__device__ __forceinline__ void ldsm4(uint32_t* r, uint32_t addr) {
    asm volatile("ldmatrix.sync.aligned.m8n8.x4.shared.b16 {%0,%1,%2,%3}, [%4];"
                 : "=r"(r[0]), "=r"(r[1]), "=r"(r[2]), "=r"(r[3]) : "r"(addr));
}
__device__ __forceinline__ void mma16816(float* c, const uint32_t* a, const uint32_t* b) {
    asm volatile(
        "mma.sync.aligned.m16n8k16.row.col.f32.bf16.bf16.f32 "
        "{%0,%1,%2,%3}, {%4,%5,%6,%7}, {%8,%9}, {%0,%1,%2,%3};"
        : "+f"(c[0]), "+f"(c[1]), "+f"(c[2]), "+f"(c[3])
        : "r"(a[0]), "r"(a[1]), "r"(a[2]), "r"(a[3]), "r"(b[0]), "r"(b[1]));
}

// ---------------- graph build pipeline ----------------
__global__ void zero_detect_k(const unsigned int* __restrict__ p) {
    int i = blockIdx.x * blockDim.x + threadIdx.x;
    if (i < NNODES) g_cnt[i] = 0;
    if (blockIdx.x == 0) {
        __shared__ int s_any;
        if (threadIdx.x == 0) s_any = 0;
        __syncthreads();
        for (int k = threadIdx.x; k < 2048; k += blockDim.x)
            if (p[2 * k + 1] != 0u) s_any = 1;
        __syncthreads();
        if (threadIdx.x == 0) g_is64 = (s_any == 0) ? 1 : 0;
    }
}
__device__ __forceinline__ int edge_val(const void* ei, size_t idx, int is64) {
    if (is64) return (int)((const long long*)ei)[idx];
    return ((const int*)ei)[idx];
}
__global__ void count_k(const void* __restrict__ ei, int E) {
    int e = blockIdx.x * blockDim.x + threadIdx.x;
    if (e >= E) return;
    atomicAdd(&g_cnt[edge_val(ei, (size_t)E + e, g_is64)], 1);
}
__global__ void scan1_k() {
    __shared__ int sm[1024];
    int b = blockIdx.x, tid = threadIdx.x;
    int i = b * 1024 + tid;
    int v = (i < NNODES) ? g_cnt[i] : 0;
    if (i < NNODES) g_dinv[i] = rsqrtf((float)(v + 1));
    sm[tid] = v;
    __syncthreads();
    #pragma unroll
    for (int d = 1; d < 1024; d <<= 1) {
        int t = (tid >= d) ? sm[tid - d] : 0;
        __syncthreads();
        sm[tid] += t;
        __syncthreads();
    }
    if (i < NNODES) g_rowptr[i] = sm[tid] - v;
    if (tid == 1023) g_bsum[b] = sm[1023];
}
// fused scan2+scan3: each block redundantly scans the 49 block sums.
__global__ void scan3_k() {
    __shared__ int sb[NB];
    __shared__ int s_pre;
    int tid = threadIdx.x;
    if (tid < NB) sb[tid] = g_bsum[tid];
    __syncthreads();
    if (tid == 0) {
        int acc = 0;
        for (int k = 0; k < (int)blockIdx.x; k++) acc += sb[k];
        s_pre = acc;
        if (blockIdx.x == 0) {
            int tot = 0;
            for (int k = 0; k < NB; k++) tot += sb[k];
            g_rowptr[NNODES] = tot;
        }
    }
    __syncthreads();
    int i = blockIdx.x * 1024 + tid;
    if (i < NNODES) {
        int r = g_rowptr[i] + s_pre;
        g_rowptr[i] = r;
        g_cursor[i] = r;
    }
}
__global__ void fill_k(const void* __restrict__ ei, int E) {
    int e = blockIdx.x * blockDim.x + threadIdx.x;
    if (e >= E) return;
    int is64 = g_is64;
    int s = edge_val(ei, (size_t)e, is64);
    int d = edge_val(ei, (size_t)E + e, is64);
    g_csrc[atomicAdd(&g_cursor[d], 1)] = s;
}

// ---------------- fused weight transpose + bf16 split (both layers) ----------------
__global__ void convW2_k(const float* __restrict__ W1, const float* __restrict__ W2) {
    int idx = blockIdx.x * blockDim.x + threadIdx.x;
    const int N1 = DIN * DH;
    if (idx < N1) {
        int k = idx / DH, n = idx % DH;
        float v = W1[idx];
        __nv_bfloat16 h = __float2bfloat16(v);
        g_w1hi[n * DIN + k] = h;
        g_w1lo[n * DIN + k] = __float2bfloat16(v - __bfloat162float(h));
    } else {
        int j = idx - N1;
        if (j < DH * DOUT) {
            int k = j / DOUT, n = j % DOUT;
            float v = W2[j];
            __nv_bfloat16 h = __float2bfloat16(v);
            g_w2hi[n * DH + k] = h;
            g_w2lo[n * DH + k] = __float2bfloat16(v - __bfloat162float(h));
        }
    }
}

// ---------------- pipelined mma.sync GEMM ----------------
#define PITCH 40
#define STG_B 10240
#define STAGE_B (4 * STG_B)
#define GEMM_SMEM (2 * STAGE_B)

__global__ void __launch_bounds__(256) gemm_mma(
    const float* __restrict__ A,
    const __nv_bfloat16* __restrict__ BThi, const __nv_bfloat16* __restrict__ BTlo,
    float* __restrict__ C, int M, int N)
{
    extern __shared__ char dsm[];
    const int K = 256;
    int tid = threadIdx.x;
    int wid = tid >> 5, lane = tid & 31;
    int wm = wid >> 1, wn = wid & 1;
    int m0 = blockIdx.y * 128;
    int n0 = blockIdx.x * 128;

    int aoff[2], boff[4];
    #pragma unroll
    for (int i = 0; i < 2; i++)
        aoff[i] = (wm * 32 + i * 16 + (lane & 15)) * PITCH + ((lane >> 4) << 3);
    #pragma unroll
    for (int j = 0; j < 4; j++)
        boff[j] = (wn * 64 + j * 16 + (lane & 7) + (((lane >> 4) & 1) << 3)) * PITCH
                + (((lane >> 3) & 1) << 3);

    uint32_t uds = smem_u32(dsm);

    float acc[2][8][4];
    #pragma unroll
    for (int i = 0; i < 2; i++)
        #pragma unroll
        for (int j = 0; j < 8; j++)
            #pragma unroll
            for (int q = 0; q < 4; q++) acc[i][j][q] = 0.f;

    int lrow = tid >> 1;
    int lseg = (tid & 1) << 4;
    bool avalid = (m0 + lrow) < M;
    const float* aptr = A + (size_t)(m0 + lrow) * K + lseg;
    const __nv_bfloat16* bhptr = BThi + (size_t)(n0 + lrow) * K + lseg;
    const __nv_bfloat16* blptr = BTlo + (size_t)(n0 + lrow) * K + lseg;
    uint32_t sAs = (uint32_t)(lrow * PITCH + lseg);

    float4 av[4];
    uint4  bv[4];

    auto loadAB = [&](int c) {
        int k0 = c * 32;
        #pragma unroll
        for (int q = 0; q < 4; q++)
            av[q] = avalid ? *(const float4*)(aptr + k0 + 4 * q)
                           : make_float4(0.f, 0.f, 0.f, 0.f);
        bv[0] = *(const uint4*)(bhptr + k0);
        bv[1] = *(const uint4*)(bhptr + k0 + 8);
        bv[2] = *(const uint4*)(blptr + k0);
        bv[3] = *(const uint4*)(blptr + k0 + 8);
    };

    auto stsAB = [&](int st) {
        char* base = dsm + st * STAGE_B;
        __nv_bfloat16* pAh = (__nv_bfloat16*)(base);
        __nv_bfloat16* pAl = (__nv_bfloat16*)(base + STG_B);
        __nv_bfloat16* pBh = (__nv_bfloat16*)(base + 2 * STG_B);
        __nv_bfloat16* pBl = (__nv_bfloat16*)(base + 3 * STG_B);
        uint32_t hv[8], lv[8];
        #pragma unroll
        for (int q = 0; q < 4; q++) {
            float4 v = av[q];
            __nv_bfloat16 h0 = __float2bfloat16(v.x), h1 = __float2bfloat16(v.y);
            __nv_bfloat16 h2 = __float2bfloat16(v.z), h3 = __float2bfloat16(v.w);
            { __nv_bfloat162 t; t.x = h0; t.y = h1; hv[2*q] = *(uint32_t*)&t;
              t.x = h2; t.y = h3; hv[2*q+1] = *(uint32_t*)&t; }
            lv[2*q]   = pack_bf16x2(v.x - __bfloat162float(h0), v.y - __bfloat162float(h1));
            lv[2*q+1] = pack_bf16x2(v.z - __bfloat162float(h2), v.w - __bfloat162float(h3));
        }
        *(uint4*)&pAh[sAs]     = make_uint4(hv[0], hv[1], hv[2], hv[3]);
        *(uint4*)&pAh[sAs + 8] = make_uint4(hv[4], hv[5], hv[6], hv[7]);
        *(uint4*)&pAl[sAs]     = make_uint4(lv[0], lv[1], lv[2], lv[3]);
        *(uint4*)&pAl[sAs + 8] = make_uint4(lv[4], lv[5], lv[6], lv[7]);
        *(uint4*)&pBh[sAs]     = bv[0];
        *(uint4*)&pBh[sAs + 8] = bv[1];
        *(uint4*)&pBl[sAs]     = bv[2];
        *(uint4*)&pBl[sAs + 8] = bv[3];
    };

    auto compute = [&](int st) {
        uint32_t b0 = uds + st * STAGE_B;
        #pragma unroll
        for (int ks = 0; ks < 2; ks++) {
            int ke = ks * 16;
            uint32_t ah[2][4], al[2][4];
            #pragma unroll
            for (int i = 0; i < 2; i++) {
                ldsm4(ah[i], b0 + (uint32_t)(aoff[i] + ke) * 2);
                ldsm4(al[i], b0 + STG_B + (uint32_t)(aoff[i] + ke) * 2);
            }
            uint32_t bh[4][4], bl[4][4];
            #pragma unroll
            for (int j = 0; j < 4; j++) {
                ldsm4(bh[j], b0 + 2 * STG_B + (uint32_t)(boff[j] + ke) * 2);
                ldsm4(bl[j], b0 + 3 * STG_B + (uint32_t)(boff[j] + ke) * 2);
            }
            #pragma unroll
            for (int i = 0; i < 2; i++)
                #pragma unroll
                for (int j = 0; j < 8; j++) {
                    const uint32_t* fh = &bh[j >> 1][(j & 1) * 2];
                    const uint32_t* fl = &bl[j >> 1][(j & 1) * 2];
                    mma16816(acc[i][j], ah[i], fh);
                    mma16816(acc[i][j], ah[i], fl);
                    mma16816(acc[i][j], al[i], fh);
                }
        }
    };

    loadAB(0);
    stsAB(0);
    __syncthreads();

    for (int c = 0; c < K / 32; c++) {
        if (c < K / 32 - 1) loadAB(c + 1);
        compute(c & 1);
        if (c < K / 32 - 1) stsAB((c + 1) & 1);
        __syncthreads();
    }

    #pragma unroll
    for (int i = 0; i < 2; i++) {
        int rr = m0 + wm * 32 + i * 16 + (lane >> 2);
        #pragma unroll
        for (int j = 0; j < 8; j++) {
            int cc = n0 + wn * 64 + j * 8 + ((lane & 3) << 1);
            if (rr < M)
                *(float2*)(C + (size_t)rr * N + cc) = make_float2(acc[i][j][0], acc[i][j][1]);
            if (rr + 8 < M)
                *(float2*)(C + (size_t)(rr + 8) * N + cc) = make_float2(acc[i][j][2], acc[i][j][3]);
        }
    }
}

// ---------------- aggregation: warp-per-node, barrier-free ----------------
// NV slabs of 128 cols; UF edges in flight per inner step.
template <int NV, int UF>
__global__ void __launch_bounds__(256) agg_warp(
    const float* __restrict__ h, const float* __restrict__ bias,
    float* __restrict__ out)
{
    const int D = NV * 128;
    int lane = threadIdx.x & 31;
    int n = blockIdx.x * 8 + (threadIdx.x >> 5);
    if (n >= NNODES) return;

    float dn = g_dinv[n];
    float4 acc[NV];
    const float* hn = h + (size_t)n * D + lane * 4;
    #pragma unroll
    for (int v = 0; v < NV; v++) {
        float4 t = *(const float4*)(hn + v * 128);
        acc[v] = make_float4(t.x * dn, t.y * dn, t.z * dn, t.w * dn);
    }

    int e0 = g_rowptr[n], e1 = g_rowptr[n + 1];
    for (int base = e0; base < e1; base += 32) {
        int k = base + lane;
        int s = 0;
        float w = 0.f;
        if (k < e1) {
            s = g_csrc[k];
            w = g_dinv[s];
        }
        int cnt = min(32, e1 - base);
        int j = 0;
        for (; j + UF <= cnt; j += UF) {
            int   su[UF];
            float wu[UF];
            #pragma unroll
            for (int u = 0; u < UF; u++) {
                su[u] = __shfl_sync(0xFFFFFFFFu, s, j + u);
                wu[u] = __shfl_sync(0xFFFFFFFFu, w, j + u);
            }
            float4 t[UF][NV];
            #pragma unroll
            for (int u = 0; u < UF; u++) {
                const float* p = h + (size_t)su[u] * D + lane * 4;
                #pragma unroll
                for (int v = 0; v < NV; v++)
                    t[u][v] = *(const float4*)(p + v * 128);
            }
            #pragma unroll
            for (int u = 0; u < UF; u++)
                #pragma unroll
                for (int v = 0; v < NV; v++) {
                    acc[v].x = fmaf(t[u][v].x, wu[u], acc[v].x);
                    acc[v].y = fmaf(t[u][v].y, wu[u], acc[v].y);
                    acc[v].z = fmaf(t[u][v].z, wu[u], acc[v].z);
                    acc[v].w = fmaf(t[u][v].w, wu[u], acc[v].w);
                }
        }
        for (; j < cnt; j++) {
            int   sj = __shfl_sync(0xFFFFFFFFu, s, j);
            float wj = __shfl_sync(0xFFFFFFFFu, w, j);
            const float* pj = h + (size_t)sj * D + lane * 4;
            #pragma unroll
            for (int v = 0; v < NV; v++) {
                float4 t = *(const float4*)(pj + v * 128);
                acc[v].x = fmaf(t.x, wj, acc[v].x);
                acc[v].y = fmaf(t.y, wj, acc[v].y);
                acc[v].z = fmaf(t.z, wj, acc[v].z);
                acc[v].w = fmaf(t.w, wj, acc[v].w);
            }
        }
    }

    float* on = out + (size_t)n * D + lane * 4;
    #pragma unroll
    for (int v = 0; v < NV; v++) {
        float4 b = *(const float4*)(bias + v * 128 + lane * 4);
        float4 o;
        o.x = fmaxf(fmaf(acc[v].x, dn, b.x), 0.f);
        o.y = fmaxf(fmaf(acc[v].y, dn, b.y), 0.f);
        o.z = fmaxf(fmaf(acc[v].z, dn, b.z), 0.f);
        o.w = fmaxf(fmaf(acc[v].w, dn, b.w), 0.f);
        *(float4*)(on + v * 128) = o;
    }
}

// ---------------- launch (R11 topology) ----------------
static cudaStream_t g_s2 = nullptr;
static cudaEvent_t  g_evF = nullptr, g_evJ = nullptr;

extern "C" void kernel_launch(void* const* d_in, const int* in_sizes, int n_in,
                              void* d_out, int out_size)
{
    const float* x  = (const float*)d_in[0];
    const void*  ei = d_in[1];
    const float* W1 = (const float*)d_in[2];
    const float* b1 = (const float*)d_in[3];
    const float* W2 = (const float*)d_in[4];
    const float* b2 = (const float*)d_in[5];

    int E = in_sizes[1] / 2;
    if (E > MAX_E) E = MAX_E;

    float *h1, *o1, *h2;
    __nv_bfloat16 *w1h, *w1l, *w2h, *w2l;
    cudaGetSymbolAddress((void**)&h1, g_h1);
    cudaGetSymbolAddress((void**)&o1, g_o1);
    cudaGetSymbolAddress((void**)&h2, g_h2);
    cudaGetSymbolAddress((void**)&w1h, g_w1hi);
    cudaGetSymbolAddress((void**)&w1l, g_w1lo);
    cudaGetSymbolAddress((void**)&w2h, g_w2hi);
    cudaGetSymbolAddress((void**)&w2l, g_w2lo);

    if (!g_s2) {
        cudaStreamCreateWithFlags(&g_s2, cudaStreamNonBlocking);
        cudaEventCreateWithFlags(&g_evF, cudaEventDisableTiming);
        cudaEventCreateWithFlags(&g_evJ, cudaEventDisableTiming);
        cudaFuncSetAttribute(gemm_mma, cudaFuncAttributeMaxDynamicSharedMemorySize, GEMM_SMEM);
    }

    // fork: graph build on side stream (overlaps convW + GEMM1)
    cudaEventRecord(g_evF, 0);
    cudaStreamWaitEvent(g_s2, g_evF, 0);

    zero_detect_k<<<(NNODES + 255) / 256, 256, 0, g_s2>>>((const unsigned int*)ei);
    count_k<<<(E + 255) / 256, 256, 0, g_s2>>>(ei, E);
    scan1_k<<<NB, 1024, 0, g_s2>>>();
    scan3_k<<<NB, 1024, 0, g_s2>>>();
    fill_k<<<(E + 255) / 256, 256, 0, g_s2>>>(ei, E);
    cudaEventRecord(g_evJ, g_s2);

    // main stream: weights + GEMM1
    convW2_k<<<(DIN * DH + DH * DOUT + 255) / 256, 256>>>(W1, W2);
    dim3 g1(DH / 128, MTILES);
    gemm_mma<<<g1, 256, GEMM_SMEM>>>(x, w1h, w1l, h1, NNODES, DH);

    // join, then sequential tail (proven-fast topology)
    cudaStreamWaitEvent(0, g_evJ, 0);

    const int AGG_GRID = (NNODES + 7) / 8;
    agg_warp<2, 4><<<AGG_GRID, 256>>>(h1, b1, o1);

    dim3 g2(DOUT / 128, MTILES);
    gemm_mma<<<g2, 256, GEMM_SMEM>>>(o1, w2h, w2l, h2, NNODES, DOUT);
    agg_warp<1, 8><<<AGG_GRID, 256>>>(h2, b2, (float*)d_out);
}

// round 16
// speedup vs baseline: 1.4376x; 1.4376x over previous
#include <cuda_runtime.h>
#include <cuda_bf16.h>
#include <cstdint>

#define NNODES 50000
#define DIN    256
#define DH     256
#define DOUT   128
#define MAX_E  1600000
#define NB     ((NNODES + 1023) / 1024)
#define MTILES ((NNODES + 127) / 128)

// ---------------- static device scratch ----------------
__device__ float g_h1[(size_t)NNODES * DH];
__device__ float g_o1[(size_t)NNODES * DH];
__device__ float g_h2[(size_t)NNODES * DOUT];
__device__ float g_dinv[NNODES];
__device__ int   g_cnt[NNODES];
__device__ int   g_rowptr[NNODES + 1];
__device__ int   g_cursor[NNODES];
__device__ int   g_csrc[MAX_E];
__device__ int   g_bsum[NB];
__device__ int   g_bpre[NB];
__device__ int   g_is64;
__device__ __nv_bfloat16 g_w1hi[DH * DIN];
__device__ __nv_bfloat16 g_w1lo[DH * DIN];
__device__ __nv_bfloat16 g_w2hi[DOUT * DH];
__device__ __nv_bfloat16 g_w2lo[DOUT * DH];

// ---------------- small helpers ----------------
__device__ __forceinline__ uint32_t smem_u32(const void* p) {
    uint32_t a;
    asm("{ .reg .u64 t; cvta.to.shared.u64 t, %1; cvt.u32.u64 %0, t; }" : "=r"(a) : "l"(p));
    return a;
}
__device__ __forceinline__ uint32_t pack_bf16x2(float a, float b) {
    __nv_bfloat162 t;
    t.x = __float2bfloat16(a);
    t.y = __float2bfloat16(b);
    return *(uint32_t*)&t;
}
__device__ __forceinline__ void ldsm4(uint32_t* r, uint32_t addr) {
    asm volatile("ldmatrix.sync.aligned.m8n8.x4.shared.b16 {%0,%1,%2,%3}, [%4];"
                 : "=r"(r[0]), "=r"(r[1]), "=r"(r[2]), "=r"(r[3]) : "r"(addr));
}
__device__ __forceinline__ void mma16816(float* c, const uint32_t* a, const uint32_t* b) {
    asm volatile(
        "mma.sync.aligned.m16n8k16.row.col.f32.bf16.bf16.f32 "
        "{%0,%1,%2,%3}, {%4,%5,%6,%7}, {%8,%9}, {%0,%1,%2,%3};"
        : "+f"(c[0]), "+f"(c[1]), "+f"(c[2]), "+f"(c[3])
        : "r"(a[0]), "r"(a[1]), "r"(a[2]), "r"(a[3]), "r"(b[0]), "r"(b[1]));
}

// ---------------- graph build pipeline ----------------
__global__ void detect_k(const unsigned int* __restrict__ p) {
    __shared__ int s_any;
    if (threadIdx.x == 0) s_any = 0;
    __syncthreads();
    for (int i = threadIdx.x; i < 2048; i += blockDim.x)
        if (p[2 * i + 1] != 0u) s_any = 1;
    __syncthreads();
    if (threadIdx.x == 0) g_is64 = (s_any == 0) ? 1 : 0;
}
__global__ void zero_k() {
    int i = blockIdx.x * blockDim.x + threadIdx.x;
    if (i < NNODES) g_cnt[i] = 0;
}
__device__ __forceinline__ int edge_val(const void* ei, size_t idx, int is64) {
    if (is64) return (int)((const long long*)ei)[idx];
    return ((const int*)ei)[idx];
}
__global__ void count_k(const void* __restrict__ ei, int E) {
    int e = blockIdx.x * blockDim.x + threadIdx.x;
    if (e >= E) return;
    atomicAdd(&g_cnt[edge_val(ei, (size_t)E + e, g_is64)], 1);
}
__global__ void scan1_k() {
    __shared__ int sm[1024];
    int b = blockIdx.x, tid = threadIdx.x;
    int i = b * 1024 + tid;
    int v = (i < NNODES) ? g_cnt[i] : 0;
    if (i < NNODES) g_dinv[i] = rsqrtf((float)(v + 1));
    sm[tid] = v;
    __syncthreads();
    #pragma unroll
    for (int d = 1; d < 1024; d <<= 1) {
        int t = (tid >= d) ? sm[tid - d] : 0;
        __syncthreads();
        sm[tid] += t;
        __syncthreads();
    }
    if (i < NNODES) g_rowptr[i] = sm[tid] - v;
    if (tid == 1023) g_bsum[b] = sm[1023];
}
__global__ void scan2_k() {
    __shared__ int sm[64];
    int tid = threadIdx.x;
    int v = (tid < NB) ? g_bsum[tid] : 0;
    sm[tid] = v;
    __syncthreads();
    #pragma unroll
    for (int d = 1; d < 64; d <<= 1) {
        int t = (tid >= d) ? sm[tid - d] : 0;
        __syncthreads();
        sm[tid] += t;
        __syncthreads();
    }
    if (tid < NB) g_bpre[tid] = sm[tid] - v;
    if (tid == NB - 1) g_rowptr[NNODES] = sm[tid];
}
__global__ void scan3_k() {
    int i = blockIdx.x * 1024 + threadIdx.x;
    if (i < NNODES) {
        int r = g_rowptr[i] + g_bpre[blockIdx.x];
        g_rowptr[i] = r;
        g_cursor[i] = r;
    }
}
__global__ void fill_k(const void* __restrict__ ei, int E) {
    int e = blockIdx.x * blockDim.x + threadIdx.x;
    if (e >= E) return;
    int is64 = g_is64;
    int s = edge_val(ei, (size_t)e, is64);
    int d = edge_val(ei, (size_t)E + e, is64);
    g_csrc[atomicAdd(&g_cursor[d], 1)] = s;
}

// ---------------- weight transpose + bf16 split ----------------
__global__ void convW_k(const float* __restrict__ W, __nv_bfloat16* __restrict__ Thi,
                        __nv_bfloat16* __restrict__ Tlo, int K, int N) {
    int idx = blockIdx.x * blockDim.x + threadIdx.x;
    if (idx >= K * N) return;
    int k = idx / N, n = idx % N;
    float v = W[idx];
    __nv_bfloat16 h = __float2bfloat16(v);
    Thi[n * K + k] = h;
    Tlo[n * K + k] = __float2bfloat16(v - __bfloat162float(h));
}

// ---------------- pipelined mma.sync GEMM ----------------
#define PITCH 40
#define STG_B 10240
#define STAGE_B (4 * STG_B)
#define GEMM_SMEM (2 * STAGE_B)

__global__ void __launch_bounds__(256) gemm_mma(
    const float* __restrict__ A,
    const __nv_bfloat16* __restrict__ BThi, const __nv_bfloat16* __restrict__ BTlo,
    float* __restrict__ C, int M, int N)
{
    extern __shared__ char dsm[];
    const int K = 256;
    int tid = threadIdx.x;
    int wid = tid >> 5, lane = tid & 31;
    int wm = wid >> 1, wn = wid & 1;
    int m0 = blockIdx.y * 128;
    int n0 = blockIdx.x * 128;

    int aoff[2], boff[4];
    #pragma unroll
    for (int i = 0; i < 2; i++)
        aoff[i] = (wm * 32 + i * 16 + (lane & 15)) * PITCH + ((lane >> 4) << 3);
    #pragma unroll
    for (int j = 0; j < 4; j++)
        boff[j] = (wn * 64 + j * 16 + (lane & 7) + (((lane >> 4) & 1) << 3)) * PITCH
                + (((lane >> 3) & 1) << 3);

    uint32_t uds = smem_u32(dsm);

    float acc[2][8][4];
    #pragma unroll
    for (int i = 0; i < 2; i++)
        #pragma unroll
        for (int j = 0; j < 8; j++)
            #pragma unroll
            for (int q = 0; q < 4; q++) acc[i][j][q] = 0.f;

    int lrow = tid >> 1;
    int lseg = (tid & 1) << 4;
    bool avalid = (m0 + lrow) < M;
    const float* aptr = A + (size_t)(m0 + lrow) * K + lseg;
    const __nv_bfloat16* bhptr = BThi + (size_t)(n0 + lrow) * K + lseg;
    const __nv_bfloat16* blptr = BTlo + (size_t)(n0 + lrow) * K + lseg;
    uint32_t sAs = (uint32_t)(lrow * PITCH + lseg);

    float4 av[4];
    uint4  bv[4];

    auto loadAB = [&](int c) {
        int k0 = c * 32;
        #pragma unroll
        for (int q = 0; q < 4; q++)
            av[q] = avalid ? *(const float4*)(aptr + k0 + 4 * q)
                           : make_float4(0.f, 0.f, 0.f, 0.f);
        bv[0] = *(const uint4*)(bhptr + k0);
        bv[1] = *(const uint4*)(bhptr + k0 + 8);
        bv[2] = *(const uint4*)(blptr + k0);
        bv[3] = *(const uint4*)(blptr + k0 + 8);
    };

    auto stsAB = [&](int st) {
        char* base = dsm + st * STAGE_B;
        __nv_bfloat16* pAh = (__nv_bfloat16*)(base);
        __nv_bfloat16* pAl = (__nv_bfloat16*)(base + STG_B);
        __nv_bfloat16* pBh = (__nv_bfloat16*)(base + 2 * STG_B);
        __nv_bfloat16* pBl = (__nv_bfloat16*)(base + 3 * STG_B);
        uint32_t hv[8], lv[8];
        #pragma unroll
        for (int q = 0; q < 4; q++) {
            float4 v = av[q];
            __nv_bfloat16 h0 = __float2bfloat16(v.x), h1 = __float2bfloat16(v.y);
            __nv_bfloat16 h2 = __float2bfloat16(v.z), h3 = __float2bfloat16(v.w);
            { __nv_bfloat162 t; t.x = h0; t.y = h1; hv[2*q] = *(uint32_t*)&t;
              t.x = h2; t.y = h3; hv[2*q+1] = *(uint32_t*)&t; }
            lv[2*q]   = pack_bf16x2(v.x - __bfloat162float(h0), v.y - __bfloat162float(h1));
            lv[2*q+1] = pack_bf16x2(v.z - __bfloat162float(h2), v.w - __bfloat162float(h3));
        }
        *(uint4*)&pAh[sAs]     = make_uint4(hv[0], hv[1], hv[2], hv[3]);
        *(uint4*)&pAh[sAs + 8] = make_uint4(hv[4], hv[5], hv[6], hv[7]);
        *(uint4*)&pAl[sAs]     = make_uint4(lv[0], lv[1], lv[2], lv[3]);
        *(uint4*)&pAl[sAs + 8] = make_uint4(lv[4], lv[5], lv[6], lv[7]);
        *(uint4*)&pBh[sAs]     = bv[0];
        *(uint4*)&pBh[sAs + 8] = bv[1];
        *(uint4*)&pBl[sAs]     = bv[2];
        *(uint4*)&pBl[sAs + 8] = bv[3];
    };

    auto compute = [&](int st) {
        uint32_t b0 = uds + st * STAGE_B;
        #pragma unroll
        for (int ks = 0; ks < 2; ks++) {
            int ke = ks * 16;
            uint32_t ah[2][4], al[2][4];
            #pragma unroll
            for (int i = 0; i < 2; i++) {
                ldsm4(ah[i], b0 + (uint32_t)(aoff[i] + ke) * 2);
                ldsm4(al[i], b0 + STG_B + (uint32_t)(aoff[i] + ke) * 2);
            }
            uint32_t bh[4][4], bl[4][4];
            #pragma unroll
            for (int j = 0; j < 4; j++) {
                ldsm4(bh[j], b0 + 2 * STG_B + (uint32_t)(boff[j] + ke) * 2);
                ldsm4(bl[j], b0 + 3 * STG_B + (uint32_t)(boff[j] + ke) * 2);
            }
            #pragma unroll
            for (int i = 0; i < 2; i++)
                #pragma unroll
                for (int j = 0; j < 8; j++) {
                    const uint32_t* fh = &bh[j >> 1][(j & 1) * 2];
                    const uint32_t* fl = &bl[j >> 1][(j & 1) * 2];
                    mma16816(acc[i][j], ah[i], fh);
                    mma16816(acc[i][j], ah[i], fl);
                    mma16816(acc[i][j], al[i], fh);
                }
        }
    };

    loadAB(0);
    stsAB(0);
    __syncthreads();

    for (int c = 0; c < K / 32; c++) {
        if (c < K / 32 - 1) loadAB(c + 1);
        compute(c & 1);
        if (c < K / 32 - 1) stsAB((c + 1) & 1);
        __syncthreads();
    }

    #pragma unroll
    for (int i = 0; i < 2; i++) {
        int rr = m0 + wm * 32 + i * 16 + (lane >> 2);
        #pragma unroll
        for (int j = 0; j < 8; j++) {
            int cc = n0 + wn * 64 + j * 8 + ((lane & 3) << 1);
            if (rr < M)
                *(float2*)(C + (size_t)rr * N + cc) = make_float2(acc[i][j][0], acc[i][j][1]);
            if (rr + 8 < M)
                *(float2*)(C + (size_t)(rr + 8) * N + cc) = make_float2(acc[i][j][2], acc[i][j][3]);
        }
    }
}

// ---------------- aggregation: warp-per-node, barrier-free ----------------
// D = 128*NV. Lane owns cols [v*128 + lane*4, +4) per slab v -> fully coalesced
// float4 loads (warp covers 512B contiguous per slab). Edge ids staged in
// registers, broadcast via shfl; inner loop unrolled x4 for MLP.
template <int NV>
__global__ void __launch_bounds__(256) agg_warp(
    const float* __restrict__ h, const float* __restrict__ bias,
    float* __restrict__ out)
{
    const int D = NV * 128;
    int lane = threadIdx.x & 31;
    int n = blockIdx.x * 8 + (threadIdx.x >> 5);
    if (n >= NNODES) return;

    float dn = g_dinv[n];
    float4 acc[NV];
    const float* hn = h + (size_t)n * D + lane * 4;
    #pragma unroll
    for (int v = 0; v < NV; v++) {
        float4 t = *(const float4*)(hn + v * 128);
        acc[v] = make_float4(t.x * dn, t.y * dn, t.z * dn, t.w * dn);
    }

    int e0 = g_rowptr[n], e1 = g_rowptr[n + 1];
    for (int base = e0; base < e1; base += 32) {
        int k = base + lane;
        int s = 0;
        float w = 0.f;
        if (k < e1) {
            s = g_csrc[k];
            w = g_dinv[s];
        }
        int cnt = min(32, e1 - base);
        int j = 0;
        for (; j + 4 <= cnt; j += 4) {
            int   s0 = __shfl_sync(0xFFFFFFFFu, s, j);
            int   s1 = __shfl_sync(0xFFFFFFFFu, s, j + 1);
            int   s2 = __shfl_sync(0xFFFFFFFFu, s, j + 2);
            int   s3 = __shfl_sync(0xFFFFFFFFu, s, j + 3);
            float w0 = __shfl_sync(0xFFFFFFFFu, w, j);
            float w1 = __shfl_sync(0xFFFFFFFFu, w, j + 1);
            float w2 = __shfl_sync(0xFFFFFFFFu, w, j + 2);
            float w3 = __shfl_sync(0xFFFFFFFFu, w, j + 3);
            const float* p0 = h + (size_t)s0 * D + lane * 4;
            const float* p1 = h + (size_t)s1 * D + lane * 4;
            const float* p2 = h + (size_t)s2 * D + lane * 4;
            const float* p3 = h + (size_t)s3 * D + lane * 4;
            float4 t0[NV], t1[NV], t2[NV], t3[NV];
            #pragma unroll
            for (int v = 0; v < NV; v++) {
                t0[v] = *(const float4*)(p0 + v * 128);
                t1[v] = *(const float4*)(p1 + v * 128);
                t2[v] = *(const float4*)(p2 + v * 128);
                t3[v] = *(const float4*)(p3 + v * 128);
            }
            #pragma unroll
            for (int v = 0; v < NV; v++) {
                acc[v].x = fmaf(t0[v].x, w0, acc[v].x);
                acc[v].y = fmaf(t0[v].y, w0, acc[v].y);
                acc[v].z = fmaf(t0[v].z, w0, acc[v].z);
                acc[v].w = fmaf(t0[v].w, w0, acc[v].w);
                acc[v].x = fmaf(t1[v].x, w1, acc[v].x);
                acc[v].y = fmaf(t1[v].y, w1, acc[v].y);
                acc[v].z = fmaf(t1[v].z, w1, acc[v].z);
                acc[v].w = fmaf(t1[v].w, w1, acc[v].w);
                acc[v].x = fmaf(t2[v].x, w2, acc[v].x);
                acc[v].y = fmaf(t2[v].y, w2, acc[v].y);
                acc[v].z = fmaf(t2[v].z, w2, acc[v].z);
                acc[v].w = fmaf(t2[v].w, w2, acc[v].w);
                acc[v].x = fmaf(t3[v].x, w3, acc[v].x);
                acc[v].y = fmaf(t3[v].y, w3, acc[v].y);
                acc[v].z = fmaf(t3[v].z, w3, acc[v].z);
                acc[v].w = fmaf(t3[v].w, w3, acc[v].w);
            }
        }
        for (; j < cnt; j++) {
            int   sj = __shfl_sync(0xFFFFFFFFu, s, j);
            float wj = __shfl_sync(0xFFFFFFFFu, w, j);
            const float* pj = h + (size_t)sj * D + lane * 4;
            #pragma unroll
            for (int v = 0; v < NV; v++) {
                float4 t = *(const float4*)(pj + v * 128);
                acc[v].x = fmaf(t.x, wj, acc[v].x);
                acc[v].y = fmaf(t.y, wj, acc[v].y);
                acc[v].z = fmaf(t.z, wj, acc[v].z);
                acc[v].w = fmaf(t.w, wj, acc[v].w);
            }
        }
    }

    float* on = out + (size_t)n * D + lane * 4;
    #pragma unroll
    for (int v = 0; v < NV; v++) {
        float4 b = *(const float4*)(bias + v * 128 + lane * 4);
        float4 o;
        o.x = fmaxf(fmaf(acc[v].x, dn, b.x), 0.f);
        o.y = fmaxf(fmaf(acc[v].y, dn, b.y), 0.f);
        o.z = fmaxf(fmaf(acc[v].z, dn, b.z), 0.f);
        o.w = fmaxf(fmaf(acc[v].w, dn, b.w), 0.f);
        *(float4*)(on + v * 128) = o;
    }
}

// ---------------- launch ----------------
static cudaStream_t g_s2 = nullptr;
static cudaEvent_t  g_evF = nullptr, g_evJ = nullptr;

extern "C" void kernel_launch(void* const* d_in, const int* in_sizes, int n_in,
                              void* d_out, int out_size)
{
    const float* x  = (const float*)d_in[0];
    const void*  ei = d_in[1];
    const float* W1 = (const float*)d_in[2];
    const float* b1 = (const float*)d_in[3];
    const float* W2 = (const float*)d_in[4];
    const float* b2 = (const float*)d_in[5];

    int E = in_sizes[1] / 2;
    if (E > MAX_E) E = MAX_E;

    float *h1, *o1, *h2;
    __nv_bfloat16 *w1h, *w1l, *w2h, *w2l;
    cudaGetSymbolAddress((void**)&h1, g_h1);
    cudaGetSymbolAddress((void**)&o1, g_o1);
    cudaGetSymbolAddress((void**)&h2, g_h2);
    cudaGetSymbolAddress((void**)&w1h, g_w1hi);
    cudaGetSymbolAddress((void**)&w1l, g_w1lo);
    cudaGetSymbolAddress((void**)&w2h, g_w2hi);
    cudaGetSymbolAddress((void**)&w2l, g_w2lo);

    if (!g_s2) {
        cudaStreamCreateWithFlags(&g_s2, cudaStreamNonBlocking);
        cudaEventCreateWithFlags(&g_evF, cudaEventDisableTiming);
        cudaEventCreateWithFlags(&g_evJ, cudaEventDisableTiming);
        cudaFuncSetAttribute(gemm_mma, cudaFuncAttributeMaxDynamicSharedMemorySize, GEMM_SMEM);
    }

    cudaEventRecord(g_evF, 0);
    cudaStreamWaitEvent(g_s2, g_evF, 0);

    detect_k<<<1, 256, 0, g_s2>>>((const unsigned int*)ei);
    zero_k<<<(NNODES + 255) / 256, 256, 0, g_s2>>>();
    count_k<<<(E + 255) / 256, 256, 0, g_s2>>>(ei, E);
    scan1_k<<<NB, 1024, 0, g_s2>>>();
    scan2_k<<<1, 64, 0, g_s2>>>();
    scan3_k<<<NB, 1024, 0, g_s2>>>();
    fill_k<<<(E + 255) / 256, 256, 0, g_s2>>>(ei, E);

    convW_k<<<(DIN * DH + 255) / 256, 256>>>(W1, w1h, w1l, DIN, DH);
    convW_k<<<(DH * DOUT + 255) / 256, 256>>>(W2, w2h, w2l, DH, DOUT);

    dim3 g1(DH / 128, MTILES);
    gemm_mma<<<g1, 256, GEMM_SMEM>>>(x, w1h, w1l, h1, NNODES, DH);

    cudaEventRecord(g_evJ, g_s2);
    cudaStreamWaitEvent(0, g_evJ, 0);

    const int AGG_GRID = (NNODES + 7) / 8;
    agg_warp<2><<<AGG_GRID, 256>>>(h1, b1, o1);

    dim3 g2(DOUT / 128, MTILES);
    gemm_mma<<<g2, 256, GEMM_SMEM>>>(o1, w2h, w2l, h2, NNODES, DOUT);
    agg_warp<1><<<AGG_GRID, 256>>>(h2, b2, (float*)d_out);
}

// round 17
// speedup vs baseline: 1.9070x; 1.3265x over previous
#include <cuda_runtime.h>
#include <cuda_fp16.h>
#include <cstdint>

#define NNODES 50000
#define DIN    256
#define DH     256
#define DOUT   128
#define MAX_E  1600000
#define NB     ((NNODES + 1023) / 1024)
#define MTILES ((NNODES + 127) / 128)

// ---------------- static device scratch ----------------
__device__ float g_h1[(size_t)NNODES * DH];
__device__ float g_o1[(size_t)NNODES * DH];
__device__ float g_h2[(size_t)NNODES * DOUT];
__device__ float g_dinv[NNODES];
__device__ int   g_cnt[NNODES];
__device__ int   g_rowptr[NNODES + 1];
__device__ int   g_cursor[NNODES];
__device__ int   g_csrc[MAX_E];
__device__ int   g_bsum[NB];
__device__ int   g_bpre[NB];
__device__ int   g_is64;
__device__ __half g_w1h[DH * DIN];
__device__ __half g_w2h[DOUT * DH];

// ---------------- small helpers ----------------
__device__ __forceinline__ uint32_t smem_u32(const void* p) {
    uint32_t a;
    asm("{ .reg .u64 t; cvta.to.shared.u64 t, %1; cvt.u32.u64 %0, t; }" : "=r"(a) : "l"(p));
    return a;
}
__device__ __forceinline__ void ldsm4(uint32_t* r, uint32_t addr) {
    asm volatile("ldmatrix.sync.aligned.m8n8.x4.shared.b16 {%0,%1,%2,%3}, [%4];"
                 : "=r"(r[0]), "=r"(r[1]), "=r"(r[2]), "=r"(r[3]) : "r"(addr));
}
__device__ __forceinline__ void mma16816h(float* c, const uint32_t* a, const uint32_t* b) {
    asm volatile(
        "mma.sync.aligned.m16n8k16.row.col.f32.f16.f16.f32 "
        "{%0,%1,%2,%3}, {%4,%5,%6,%7}, {%8,%9}, {%0,%1,%2,%3};"
        : "+f"(c[0]), "+f"(c[1]), "+f"(c[2]), "+f"(c[3])
        : "r"(a[0]), "r"(a[1]), "r"(a[2]), "r"(a[3]), "r"(b[0]), "r"(b[1]));
}

// ---------------- graph build pipeline ----------------
__global__ void detect_k(const unsigned int* __restrict__ p) {
    __shared__ int s_any;
    if (threadIdx.x == 0) s_any = 0;
    __syncthreads();
    for (int i = threadIdx.x; i < 2048; i += blockDim.x)
        if (p[2 * i + 1] != 0u) s_any = 1;
    __syncthreads();
    if (threadIdx.x == 0) g_is64 = (s_any == 0) ? 1 : 0;
}
__global__ void zero_k() {
    int i = blockIdx.x * blockDim.x + threadIdx.x;
    if (i < NNODES) g_cnt[i] = 0;
}
__device__ __forceinline__ int edge_val(const void* ei, size_t idx, int is64) {
    if (is64) return (int)((const long long*)ei)[idx];
    return ((const int*)ei)[idx];
}
__global__ void count_k(const void* __restrict__ ei, int E) {
    int e = blockIdx.x * blockDim.x + threadIdx.x;
    if (e >= E) return;
    atomicAdd(&g_cnt[edge_val(ei, (size_t)E + e, g_is64)], 1);
}
__global__ void scan1_k() {
    __shared__ int sm[1024];
    int b = blockIdx.x, tid = threadIdx.x;
    int i = b * 1024 + tid;
    int v = (i < NNODES) ? g_cnt[i] : 0;
    if (i < NNODES) g_dinv[i] = rsqrtf((float)(v + 1));
    sm[tid] = v;
    __syncthreads();
    #pragma unroll
    for (int d = 1; d < 1024; d <<= 1) {
        int t = (tid >= d) ? sm[tid - d] : 0;
        __syncthreads();
        sm[tid] += t;
        __syncthreads();
    }
    if (i < NNODES) g_rowptr[i] = sm[tid] - v;
    if (tid == 1023) g_bsum[b] = sm[1023];
}
__global__ void scan2_k() {
    __shared__ int sm[64];
    int tid = threadIdx.x;
    int v = (tid < NB) ? g_bsum[tid] : 0;
    sm[tid] = v;
    __syncthreads();
    #pragma unroll
    for (int d = 1; d < 64; d <<= 1) {
        int t = (tid >= d) ? sm[tid - d] : 0;
        __syncthreads();
        sm[tid] += t;
        __syncthreads();
    }
    if (tid < NB) g_bpre[tid] = sm[tid] - v;
    if (tid == NB - 1) g_rowptr[NNODES] = sm[tid];
}
__global__ void scan3_k() {
    int i = blockIdx.x * 1024 + threadIdx.x;
    if (i < NNODES) {
        int r = g_rowptr[i] + g_bpre[blockIdx.x];
        g_rowptr[i] = r;
        g_cursor[i] = r;
    }
}
__global__ void fill_k(const void* __restrict__ ei, int E) {
    int e = blockIdx.x * blockDim.x + threadIdx.x;
    if (e >= E) return;
    int is64 = g_is64;
    int s = edge_val(ei, (size_t)e, is64);
    int d = edge_val(ei, (size_t)E + e, is64);
    g_csrc[atomicAdd(&g_cursor[d], 1)] = s;
}

// ---------------- weight transpose to fp16: W[K][N] -> T[n][k] ----------------
__global__ void convW_k(const float* __restrict__ W, __half* __restrict__ T, int K, int N) {
    int idx = blockIdx.x * blockDim.x + threadIdx.x;
    if (idx >= K * N) return;
    int k = idx / N, n = idx % N;
    T[n * K + k] = __float2half(W[idx]);
}

// ---------------- pipelined fp16 mma.sync GEMM ----------------
// C[M,N] = A[M,256] @ (BT[N,256])^T, fp16 inputs, fp32 accum.
// Block 128x128x32, 8 warps (4m x 2n). 2-stage smem + register prefetch.
#define PITCH 40
#define STG_B 10240                      // one array: 128*40*2 bytes
#define STAGE_B (2 * STG_B)              // A + B per stage
#define GEMM_SMEM (2 * STAGE_B)          // 40960 bytes

__global__ void __launch_bounds__(256) gemm_mma(
    const float* __restrict__ A,
    const __half* __restrict__ BT,
    float* __restrict__ C, int M, int N)
{
    extern __shared__ char dsm[];
    const int K = 256;
    int tid = threadIdx.x;
    int wid = tid >> 5, lane = tid & 31;
    int wm = wid >> 1, wn = wid & 1;
    int m0 = blockIdx.y * 128;
    int n0 = blockIdx.x * 128;

    int aoff[2], boff[4];
    #pragma unroll
    for (int i = 0; i < 2; i++)
        aoff[i] = (wm * 32 + i * 16 + (lane & 15)) * PITCH + ((lane >> 4) << 3);
    #pragma unroll
    for (int j = 0; j < 4; j++)
        boff[j] = (wn * 64 + j * 16 + (lane & 7) + (((lane >> 4) & 1) << 3)) * PITCH
                + (((lane >> 3) & 1) << 3);

    uint32_t uds = smem_u32(dsm);

    float acc[2][8][4];
    #pragma unroll
    for (int i = 0; i < 2; i++)
        #pragma unroll
        for (int j = 0; j < 8; j++)
            #pragma unroll
            for (int q = 0; q < 4; q++) acc[i][j][q] = 0.f;

    int lrow = tid >> 1;
    int lseg = (tid & 1) << 4;
    bool avalid = (m0 + lrow) < M;
    const float* aptr = A + (size_t)(m0 + lrow) * K + lseg;
    const __half* bptr = BT + (size_t)(n0 + lrow) * K + lseg;
    uint32_t sAs = (uint32_t)(lrow * PITCH + lseg);

    float4 av[4];
    uint4  bv[2];

    auto loadAB = [&](int c) {
        int k0 = c * 32;
        #pragma unroll
        for (int q = 0; q < 4; q++)
            av[q] = avalid ? *(const float4*)(aptr + k0 + 4 * q)
                           : make_float4(0.f, 0.f, 0.f, 0.f);
        bv[0] = *(const uint4*)(bptr + k0);
        bv[1] = *(const uint4*)(bptr + k0 + 8);
    };

    auto stsAB = [&](int st) {
        char* base = dsm + st * STAGE_B;
        __half* pA = (__half*)(base);
        __half* pB = (__half*)(base + STG_B);
        uint32_t hv[8];
        #pragma unroll
        for (int q = 0; q < 4; q++) {
            float4 v = av[q];
            __half2 t0 = __floats2half2_rn(v.x, v.y);
            __half2 t1 = __floats2half2_rn(v.z, v.w);
            hv[2*q]   = *(uint32_t*)&t0;
            hv[2*q+1] = *(uint32_t*)&t1;
        }
        *(uint4*)&pA[sAs]     = make_uint4(hv[0], hv[1], hv[2], hv[3]);
        *(uint4*)&pA[sAs + 8] = make_uint4(hv[4], hv[5], hv[6], hv[7]);
        *(uint4*)&pB[sAs]     = bv[0];
        *(uint4*)&pB[sAs + 8] = bv[1];
    };

    auto compute = [&](int st) {
        uint32_t b0 = uds + st * STAGE_B;
        #pragma unroll
        for (int ks = 0; ks < 2; ks++) {
            int ke = ks * 16;
            uint32_t ah[2][4];
            #pragma unroll
            for (int i = 0; i < 2; i++)
                ldsm4(ah[i], b0 + (uint32_t)(aoff[i] + ke) * 2);
            uint32_t bh[4][4];
            #pragma unroll
            for (int j = 0; j < 4; j++)
                ldsm4(bh[j], b0 + STG_B + (uint32_t)(boff[j] + ke) * 2);
            #pragma unroll
            for (int i = 0; i < 2; i++)
                #pragma unroll
                for (int j = 0; j < 8; j++)
                    mma16816h(acc[i][j], ah[i], &bh[j >> 1][(j & 1) * 2]);
        }
    };

    loadAB(0);
    stsAB(0);
    __syncthreads();

    for (int c = 0; c < K / 32; c++) {
        if (c < K / 32 - 1) loadAB(c + 1);
        compute(c & 1);
        if (c < K / 32 - 1) stsAB((c + 1) & 1);
        __syncthreads();
    }

    #pragma unroll
    for (int i = 0; i < 2; i++) {
        int rr = m0 + wm * 32 + i * 16 + (lane >> 2);
        #pragma unroll
        for (int j = 0; j < 8; j++) {
            int cc = n0 + wn * 64 + j * 8 + ((lane & 3) << 1);
            if (rr < M)
                *(float2*)(C + (size_t)rr * N + cc) = make_float2(acc[i][j][0], acc[i][j][1]);
            if (rr + 8 < M)
                *(float2*)(C + (size_t)(rr + 8) * N + cc) = make_float2(acc[i][j][2], acc[i][j][3]);
        }
    }
}

// ---------------- aggregation: warp-per-node, barrier-free (R11-proven) ----------------
template <int NV>
__global__ void __launch_bounds__(256) agg_warp(
    const float* __restrict__ h, const float* __restrict__ bias,
    float* __restrict__ out)
{
    const int D = NV * 128;
    int lane = threadIdx.x & 31;
    int n = blockIdx.x * 8 + (threadIdx.x >> 5);
    if (n >= NNODES) return;

    float dn = g_dinv[n];
    float4 acc[NV];
    const float* hn = h + (size_t)n * D + lane * 4;
    #pragma unroll
    for (int v = 0; v < NV; v++) {
        float4 t = *(const float4*)(hn + v * 128);
        acc[v] = make_float4(t.x * dn, t.y * dn, t.z * dn, t.w * dn);
    }

    int e0 = g_rowptr[n], e1 = g_rowptr[n + 1];
    for (int base = e0; base < e1; base += 32) {
        int k = base + lane;
        int s = 0;
        float w = 0.f;
        if (k < e1) {
            s = g_csrc[k];
            w = g_dinv[s];
        }
        int cnt = min(32, e1 - base);
        int j = 0;
        for (; j + 4 <= cnt; j += 4) {
            int   s0 = __shfl_sync(0xFFFFFFFFu, s, j);
            int   s1 = __shfl_sync(0xFFFFFFFFu, s, j + 1);
            int   s2 = __shfl_sync(0xFFFFFFFFu, s, j + 2);
            int   s3 = __shfl_sync(0xFFFFFFFFu, s, j + 3);
            float w0 = __shfl_sync(0xFFFFFFFFu, w, j);
            float w1 = __shfl_sync(0xFFFFFFFFu, w, j + 1);
            float w2 = __shfl_sync(0xFFFFFFFFu, w, j + 2);
            float w3 = __shfl_sync(0xFFFFFFFFu, w, j + 3);
            const float* p0 = h + (size_t)s0 * D + lane * 4;
            const float* p1 = h + (size_t)s1 * D + lane * 4;
            const float* p2 = h + (size_t)s2 * D + lane * 4;
            const float* p3 = h + (size_t)s3 * D + lane * 4;
            float4 t0[NV], t1[NV], t2[NV], t3[NV];
            #pragma unroll
            for (int v = 0; v < NV; v++) {
                t0[v] = *(const float4*)(p0 + v * 128);
                t1[v] = *(const float4*)(p1 + v * 128);
                t2[v] = *(const float4*)(p2 + v * 128);
                t3[v] = *(const float4*)(p3 + v * 128);
            }
            #pragma unroll
            for (int v = 0; v < NV; v++) {
                acc[v].x = fmaf(t0[v].x, w0, acc[v].x);
                acc[v].y = fmaf(t0[v].y, w0, acc[v].y);
                acc[v].z = fmaf(t0[v].z, w0, acc[v].z);
                acc[v].w = fmaf(t0[v].w, w0, acc[v].w);
                acc[v].x = fmaf(t1[v].x, w1, acc[v].x);
                acc[v].y = fmaf(t1[v].y, w1, acc[v].y);
                acc[v].z = fmaf(t1[v].z, w1, acc[v].z);
                acc[v].w = fmaf(t1[v].w, w1, acc[v].w);
                acc[v].x = fmaf(t2[v].x, w2, acc[v].x);
                acc[v].y = fmaf(t2[v].y, w2, acc[v].y);
                acc[v].z = fmaf(t2[v].z, w2, acc[v].z);
                acc[v].w = fmaf(t2[v].w, w2, acc[v].w);
                acc[v].x = fmaf(t3[v].x, w3, acc[v].x);
                acc[v].y = fmaf(t3[v].y, w3, acc[v].y);
                acc[v].z = fmaf(t3[v].z, w3, acc[v].z);
                acc[v].w = fmaf(t3[v].w, w3, acc[v].w);
            }
        }
        for (; j < cnt; j++) {
            int   sj = __shfl_sync(0xFFFFFFFFu, s, j);
            float wj = __shfl_sync(0xFFFFFFFFu, w, j);
            const float* pj = h + (size_t)sj * D + lane * 4;
            #pragma unroll
            for (int v = 0; v < NV; v++) {
                float4 t = *(const float4*)(pj + v * 128);
                acc[v].x = fmaf(t.x, wj, acc[v].x);
                acc[v].y = fmaf(t.y, wj, acc[v].y);
                acc[v].z = fmaf(t.z, wj, acc[v].z);
                acc[v].w = fmaf(t.w, wj, acc[v].w);
            }
        }
    }

    float* on = out + (size_t)n * D + lane * 4;
    #pragma unroll
    for (int v = 0; v < NV; v++) {
        float4 b = *(const float4*)(bias + v * 128 + lane * 4);
        float4 o;
        o.x = fmaxf(fmaf(acc[v].x, dn, b.x), 0.f);
        o.y = fmaxf(fmaf(acc[v].y, dn, b.y), 0.f);
        o.z = fmaxf(fmaf(acc[v].z, dn, b.z), 0.f);
        o.w = fmaxf(fmaf(acc[v].w, dn, b.w), 0.f);
        *(float4*)(on + v * 128) = o;
    }
}

// ---------------- launch (R11/R16-proven topology) ----------------
static cudaStream_t g_s2 = nullptr;
static cudaEvent_t  g_evF = nullptr, g_evJ = nullptr;

extern "C" void kernel_launch(void* const* d_in, const int* in_sizes, int n_in,
                              void* d_out, int out_size)
{
    const float* x  = (const float*)d_in[0];
    const void*  ei = d_in[1];
    const float* W1 = (const float*)d_in[2];
    const float* b1 = (const float*)d_in[3];
    const float* W2 = (const float*)d_in[4];
    const float* b2 = (const float*)d_in[5];

    int E = in_sizes[1] / 2;
    if (E > MAX_E) E = MAX_E;

    float *h1, *o1, *h2;
    __half *w1h, *w2h;
    cudaGetSymbolAddress((void**)&h1, g_h1);
    cudaGetSymbolAddress((void**)&o1, g_o1);
    cudaGetSymbolAddress((void**)&h2, g_h2);
    cudaGetSymbolAddress((void**)&w1h, g_w1h);
    cudaGetSymbolAddress((void**)&w2h, g_w2h);

    if (!g_s2) {
        cudaStreamCreateWithFlags(&g_s2, cudaStreamNonBlocking);
        cudaEventCreateWithFlags(&g_evF, cudaEventDisableTiming);
        cudaEventCreateWithFlags(&g_evJ, cudaEventDisableTiming);
        cudaFuncSetAttribute(gemm_mma, cudaFuncAttributeMaxDynamicSharedMemorySize, GEMM_SMEM);
    }

    cudaEventRecord(g_evF, 0);
    cudaStreamWaitEvent(g_s2, g_evF, 0);

    detect_k<<<1, 256, 0, g_s2>>>((const unsigned int*)ei);
    zero_k<<<(NNODES + 255) / 256, 256, 0, g_s2>>>();
    count_k<<<(E + 255) / 256, 256, 0, g_s2>>>(ei, E);
    scan1_k<<<NB, 1024, 0, g_s2>>>();
    scan2_k<<<1, 64, 0, g_s2>>>();
    scan3_k<<<NB, 1024, 0, g_s2>>>();
    fill_k<<<(E + 255) / 256, 256, 0, g_s2>>>(ei, E);

    convW_k<<<(DIN * DH + 255) / 256, 256>>>(W1, w1h, DIN, DH);
    convW_k<<<(DH * DOUT + 255) / 256, 256>>>(W2, w2h, DH, DOUT);

    dim3 g1(DH / 128, MTILES);
    gemm_mma<<<g1, 256, GEMM_SMEM>>>(x, w1h, h1, NNODES, DH);

    cudaEventRecord(g_evJ, g_s2);
    cudaStreamWaitEvent(0, g_evJ, 0);

    const int AGG_GRID = (NNODES + 7) / 8;
    agg_warp<2><<<AGG_GRID, 256>>>(h1, b1, o1);

    dim3 g2(DOUT / 128, MTILES);
    gemm_mma<<<g2, 256, GEMM_SMEM>>>(o1, w2h, h2, NNODES, DOUT);
    agg_warp<1><<<AGG_GRID, 256>>>(h2, b2, (float*)d_out);
}